// round 7
// baseline (speedup 1.0000x reference)
#include <cuda_runtime.h>
#include <cuda_bf16.h>

#define THREADS 512
#define VT      128000
#define VS      32000
#define KSEL    256
#define MAXB    2048

// monotone float->uint key
__device__ __forceinline__ unsigned f2k(float x) {
    unsigned u = __float_as_uint(x);
    return (u & 0x80000000u) ? ~u : (u | 0x80000000u);
}
__device__ __forceinline__ float k2f(unsigned k) {
    unsigned u = (k & 0x80000000u) ? (k & 0x7fffffffu) : ~k;
    return __uint_as_float(u);
}

__global__ void __launch_bounds__(THREADS, 3)
vocab_project_kernel(const float* __restrict__ logits,
                     const void* __restrict__ mapping,
                     float* __restrict__ out) {
    __shared__ unsigned h256[256];
    __shared__ unsigned tKey[2][MAXB], tIdx[2][MAXB];
    __shared__ float    fred[THREADS];
    __shared__ float    fred2[THREADS];
    __shared__ unsigned selKey[KSEL], selIdx[KSEL];
    __shared__ int      s_bin;
    __shared__ unsigned s_above;
    __shared__ int      nCand, selCount, nNext, s_is64;
    __shared__ unsigned s_maxkey, s_minkey;
    __shared__ float    s_mean, s_std, s_denom;

    const int tid = threadIdx.x;
    const int row = blockIdx.x;
    const float* __restrict__ rowf = logits + (size_t)row * VT;
    const float4* __restrict__ rp = (const float4*)rowf;
    float* __restrict__ orow = out + (size_t)row * VS;

    // ---- zero own output row FIRST: stores drain behind the streaming reads ----
    {
        float4 z = make_float4(0.f, 0.f, 0.f, 0.f);
        float4* op = (float4*)orow;
        for (int i = tid; i < VS / 4; i += THREADS) op[i] = z;
    }

    // ---- init + mapping dtype detect ----
    if (tid == 0) {
        const unsigned* m32 = (const unsigned*)mapping;
        int all0 = 1;
        for (int i = 1; i < 64; i += 2)
            if (m32[i] != 0u) { all0 = 0; break; }
        s_is64 = all0;
        s_denom = 0.0f;
        selCount = 0;
    }

    // ---- full pass: collect (key, idx) >= threshold ----
    // Common case: fixed threshold for ~N(0,1) rows; sampled-stats fallback
    // re-tries with an adjusted threshold for arbitrary distributions.
    float thrVal = 2.45f;               // E[count] ~ 915 for standard normal
    float stdGuess = 1.0f;
    bool haveStats = false;
    for (int attempt = 0; attempt < 10; attempt++) {
        if (tid == 0) { nCand = 0; s_maxkey = 0u; s_minkey = 0xFFFFFFFFu; }
        __syncthreads();
        // 32 floats (8 x float4) per iteration: MLP_p1 = 8
        for (int i = tid; i < VT / 32; i += THREADS) {
            const float4 v0 = rp[8 * i + 0];
            const float4 v1 = rp[8 * i + 1];
            const float4 v2 = rp[8 * i + 2];
            const float4 v3 = rp[8 * i + 3];
            const float4 v4 = rp[8 * i + 4];
            const float4 v5 = rp[8 * i + 5];
            const float4 v6 = rp[8 * i + 6];
            const float4 v7 = rp[8 * i + 7];
            float m0 = fmaxf(fmaxf(v0.x, v0.y), fmaxf(v0.z, v0.w));
            float m1 = fmaxf(fmaxf(v1.x, v1.y), fmaxf(v1.z, v1.w));
            float m2 = fmaxf(fmaxf(v2.x, v2.y), fmaxf(v2.z, v2.w));
            float m3 = fmaxf(fmaxf(v3.x, v3.y), fmaxf(v3.z, v3.w));
            float m4 = fmaxf(fmaxf(v4.x, v4.y), fmaxf(v4.z, v4.w));
            float m5 = fmaxf(fmaxf(v5.x, v5.y), fmaxf(v5.z, v5.w));
            float m6 = fmaxf(fmaxf(v6.x, v6.y), fmaxf(v6.z, v6.w));
            float m7 = fmaxf(fmaxf(v7.x, v7.y), fmaxf(v7.z, v7.w));
            float mm = fmaxf(fmaxf(fmaxf(m0, m1), fmaxf(m2, m3)),
                             fmaxf(fmaxf(m4, m5), fmaxf(m6, m7)));
            if (mm >= thrVal) {
                const float v[32] = {v0.x,v0.y,v0.z,v0.w, v1.x,v1.y,v1.z,v1.w,
                                     v2.x,v2.y,v2.z,v2.w, v3.x,v3.y,v3.z,v3.w,
                                     v4.x,v4.y,v4.z,v4.w, v5.x,v5.y,v5.z,v5.w,
                                     v6.x,v6.y,v6.z,v6.w, v7.x,v7.y,v7.z,v7.w};
#pragma unroll
                for (int j = 0; j < 32; j++) {
                    if (v[j] >= thrVal) {
                        unsigned key = f2k(v[j]);
                        int p = atomicAdd(&nCand, 1);
                        if (p < MAXB) {
                            tKey[0][p] = key;
                            tIdx[0][p] = (unsigned)(i * 32 + j);
                            atomicMax(&s_maxkey, key);
                            atomicMin(&s_minkey, key);
                        }
                    }
                }
            }
        }
        __syncthreads();
        int nc = nCand;
        if (nc >= KSEL && nc <= MAXB) break;
        if (!haveStats) {
            // sampled mean/std (rare path)
            float x = rowf[tid * (VT / THREADS)];
            fred[tid] = x;
            fred2[tid] = x * x;
            __syncthreads();
            for (int s = THREADS / 2; s > 0; s >>= 1) {
                if (tid < s) {
                    fred[tid] += fred[tid + s];
                    fred2[tid] += fred2[tid + s];
                }
                __syncthreads();
            }
            if (tid == 0) {
                float mean = fred[0] * (1.0f / THREADS);
                float var  = fred2[0] * (1.0f / THREADS) - mean * mean;
                s_mean = mean;
                s_std  = sqrtf(fmaxf(var, 1e-12f));
            }
            __syncthreads();
            stdGuess = s_std;
            float cand = s_mean + 2.45f * s_std;
            if (fabsf(cand - thrVal) < 0.05f * s_std)
                cand += (nc < KSEL) ? -0.60f * s_std : 0.35f * s_std;
            thrVal = cand;
            haveStats = true;
        } else {
            if (nc < KSEL) thrVal -= 0.60f * stdGuess + 1e-6f;
            else           thrVal += 0.35f * stdGuess + 1e-6f;
        }
        __syncthreads();
    }

    // ---- exact top-KSEL: byte-radix select starting at highest differing byte ----
    int cur = 0;
    int curN = nCand < MAXB ? nCand : MAXB;
    int need = KSEL;
    const unsigned keyxor = s_minkey ^ s_maxkey;
    int level_start = (keyxor == 0u) ? -1 : (3 - (__clz(keyxor) >> 3));
    __syncthreads();

    for (int level = level_start; level >= 0 && need > 0; level--) {
        if (curN == need) {
            for (int p = tid; p < curN; p += THREADS) {
                int q = atomicAdd(&selCount, 1);
                selKey[q] = tKey[cur][p]; selIdx[q] = tIdx[cur][p];
            }
            need = 0;
            __syncthreads();
            break;
        }
        if (tid < 256) h256[tid] = 0u;
        __syncthreads();
        const int sh = level * 8;
        for (int p = tid; p < curN; p += THREADS)
            atomicAdd(&h256[(tKey[cur][p] >> sh) & 0xFFu], 1u);
        __syncthreads();
        // single-warp top-down scan over 256 bins: find crossing bin
        if (tid < 32) {
            unsigned local[8];
            unsigned part = 0;
#pragma unroll
            for (int j = 0; j < 8; j++) {
                local[j] = h256[255 - (tid * 8 + j)];
                part += local[j];
            }
            unsigned incl = part;
#pragma unroll
            for (int off = 1; off < 32; off <<= 1) {
                unsigned v = __shfl_up_sync(0xffffffffu, incl, off);
                if (tid >= off) incl += v;
            }
            unsigned before = incl - part;
            if (before < (unsigned)need && incl >= (unsigned)need) {
                unsigned cum = before;
#pragma unroll
                for (int j = 0; j < 8; j++) {
                    unsigned c = local[j];
                    if (cum + c >= (unsigned)need) {
                        s_bin = 255 - (tid * 8 + j);
                        s_above = cum;
                        break;
                    }
                    cum += c;
                }
            }
        }
        if (tid == 0) nNext = 0;
        __syncthreads();
        const int c = s_bin;
        const int G = (int)s_above;
        const int oth = cur ^ 1;
        for (int p = tid; p < curN; p += THREADS) {
            unsigned key = tKey[cur][p];
            int byte = (int)((key >> sh) & 0xFFu);
            if (byte > c) {
                int q = atomicAdd(&selCount, 1);
                selKey[q] = key; selIdx[q] = tIdx[cur][p];
            } else if (byte == c) {
                int q = atomicAdd(&nNext, 1);
                tKey[oth][q] = key; tIdx[oth][q] = tIdx[cur][p];
            }
        }
        __syncthreads();
        need -= G;
        curN = nNext;
        cur = oth;
        __syncthreads();
    }

    // remaining entries have IDENTICAL keys; take `need` smallest indices
    if (need > 0) {
        for (int p = tid; p < curN; p += THREADS) {
            unsigned my = tIdx[cur][p];
            int rank = 0;
            for (int j = 0; j < curN; j++) rank += (tIdx[cur][j] < my);
            if (rank < need) {
                int q = atomicAdd(&selCount, 1);
                selKey[q] = tKey[cur][p]; selIdx[q] = my;
            }
        }
        __syncthreads();
    }

    // ---- max logit = global max key (tracked during collection) ----
    const float vmax = k2f(s_maxkey);

    // ---- weights + denominator (warp shfl reduce + shared atomics) ----
    float w = 0.0f;
    if (tid < KSEL) {
        w = exp2f((k2f(selKey[tid]) - vmax) * 0.36067376022224085f); // 1/(4 ln2)
        float ws = w;
#pragma unroll
        for (int off = 16; off > 0; off >>= 1)
            ws += __shfl_xor_sync(0xffffffffu, ws, off);
        if ((tid & 31) == 0) atomicAdd(&s_denom, ws);
    }
    __syncthreads();
    const float inv = 1.0f / s_denom;

    // ---- scatter: gather sid, atomic add into zeroed row (handles dups) ----
    if (tid < KSEL) {
        unsigned idx = selIdx[tid];
        int sid;
        if (s_is64) sid = (int)((const long long*)mapping)[idx];
        else        sid = ((const int*)mapping)[idx];
        atomicAdd(&orow[sid], w * inv);
    }
}

extern "C" void kernel_launch(void* const* d_in, const int* in_sizes, int n_in,
                              void* d_out, int out_size) {
    const float* logits  = (const float*)d_in[0];
    const void*  mapping = d_in[1];
    float* out = (float*)d_out;
    int rows = in_sizes[0] / VT;   // B*T = 2048
    vocab_project_kernel<<<rows, THREADS>>>(logits, mapping, out);
}